// round 10
// baseline (speedup 1.0000x reference)
#include <cuda_runtime.h>
#include <cuda_fp16.h>
#include <math.h>

#define N_NODES 100000
#define N_EDGES 1600000
#define FULL 0xffffffffu
#define NB_SCAN 391        // ceil(100000/256)
#define ZROW N_NODES       // index of the always-zero feature row
#define NGRP 12500         // node groups of 8
#define PBLKS 1184         // persistent blocks for layer2 (148 SMs * 8)

// ---- scratch (static device globals; zero at load; layer1 restores zeros) ----
__device__ int   g_count[N_NODES];
__device__ int   g_rowptr[N_NODES + 1];
__device__ float g_dinv[N_NODES];
__device__ int   g_col[N_EDGES + 64];                  // +64 pad: safe tail loads (pad reads guarded)
__device__ unsigned long long g_bstate[NB_SCAN];
__device__ __align__(16) __half g_x0h[(N_NODES + 1) * 16];  // row ZROW stays 0
__device__ __align__(16) __half g_x1h[(N_NODES + 1) * 64];  // row ZROW stays 0
__device__ __align__(16) __half g_ph [(N_NODES + 1) * 16];  // row ZROW + pads stay 0

#define H2(x) (*(__half2*)&(x))

// ---------------- 1. histogram (g_count zero on entry) ----------------
__global__ void k_hist(const int* __restrict__ ei) {
    int e4 = blockIdx.x * blockDim.x + threadIdx.x;
    if (e4 < N_EDGES / 4) {
        int4 d = ((const int4*)(ei + N_EDGES))[e4];
        atomicAdd(&g_count[d.x], 1);
        atomicAdd(&g_count[d.y], 1);
        atomicAdd(&g_count[d.z], 1);
        atomicAdd(&g_count[d.w], 1);
    }
}

// ---------------- 2. fused scan: rowptr + dinv + cursor + padx ----------------
__global__ void k_scanfused(const float* __restrict__ x) {
    __shared__ int s[256];
    __shared__ int s_prefix;
    const int tid = threadIdx.x;
    const int bid = blockIdx.x;
    const int i = bid * 256 + tid;

    int c = (i < N_NODES) ? g_count[i] : 0;
    s[tid] = c;
    __syncthreads();
    for (int off = 1; off < 256; off <<= 1) {
        int t = (tid >= off) ? s[tid - off] : 0;
        __syncthreads();
        s[tid] += t;
        __syncthreads();
    }
    int total = s[255];

    if (tid == 0) {
        if (bid == 0) {
            s_prefix = 0;
            atomicExch(&g_bstate[0], (2ULL << 32) | (unsigned int)total);
        } else {
            atomicExch(&g_bstate[bid], (1ULL << 32) | (unsigned int)total);
            int pre = 0;
            for (int j = bid - 1; j >= 0; j--) {
                unsigned long long st;
                do {
                    st = *((volatile unsigned long long*)&g_bstate[j]);
                } while ((st >> 32) == 0ULL);
                pre += (int)(st & 0xffffffffULL);
                if ((st >> 32) == 2ULL) break;
            }
            s_prefix = pre;
            atomicExch(&g_bstate[bid], (2ULL << 32) | (unsigned int)(pre + total));
        }
    }
    __syncthreads();

    if (i < N_NODES) {
        int rp = s_prefix + s[tid] - c;
        g_rowptr[i] = rp;
        float di = rsqrtf((float)c + 1.0f);
        g_dinv[i] = di;
        g_count[i] = rp;                  // absolute cursor for scatter
        __half2* o = (__half2*)(g_x0h + i * 16);
#pragma unroll
        for (int q = 0; q < 8; q++) {
            float a = (2 * q < 13)     ? di * x[i * 13 + 2 * q]     : 0.0f;
            float b = (2 * q + 1 < 13) ? di * x[i * 13 + 2 * q + 1] : 0.0f;
            o[q] = __floats2half2_rn(a, b);
        }
    }
    if (i == 0) g_rowptr[N_NODES] = N_EDGES;
}

// ---------------- 3. scatter ----------------
__global__ void k_scatter(const int* __restrict__ ei) {
    int e2 = blockIdx.x * blockDim.x + threadIdx.x;
    if (e2 < N_EDGES / 2) {
        int2 ss = ((const int2*)ei)[e2];
        int2 dd = ((const int2*)(ei + N_EDGES))[e2];
        int p0 = atomicAdd(&g_count[dd.x], 1);
        g_col[p0] = ss.x;
        int p1 = atomicAdd(&g_count[dd.y], 1);
        g_col[p1] = ss.y;
    }
}

// fp32 accumulate 2 half2 (4 floats)
__device__ __forceinline__ void acch4(float* acc, __half2 s0, __half2 s1) {
    float2 f0 = __half22float2(s0);
    float2 f1 = __half22float2(s1);
    acc[0] += f0.x; acc[1] += f0.y; acc[2] += f1.x; acc[3] += f1.y;
}

// fp32 accumulate 4 half2 (8 floats)
__device__ __forceinline__ void acch(float* acc, __half2 s0, __half2 s1,
                                     __half2 s2, __half2 s3) {
    float2 f0 = __half22float2(s0);
    float2 f1 = __half22float2(s1);
    float2 f2 = __half22float2(s2);
    float2 f3 = __half22float2(s3);
    acc[0] += f0.x; acc[1] += f0.y; acc[2] += f1.x; acc[3] += f1.y;
    acc[4] += f2.x; acc[5] += f2.y; acc[6] += f3.x; acc[7] += f3.y;
}

// ---------------- 4. layer 1 (non-persistent; + zero restore) ----------------
// block = 8 warps = 8 nodes. Phase A: 4 lanes/edge (int2), 32 edges/iter,
// shfl-distributed cols, 4-deep hadd2 tree. Phase B: redistributed GEMM 13->64.
__global__ void k_layer1(const float* __restrict__ W1,
                         const float* __restrict__ b1) {
    __shared__ float W1s[13 * 64];
    __shared__ float b1s[64];
    __shared__ float s_x[8][20];
    __shared__ float s_di[8];
    __shared__ __half2 s_oh[8][33];

    {
        int gtid = blockIdx.x * 256 + threadIdx.x;
        if (gtid < N_NODES) g_count[gtid] = 0;
        if (gtid < NB_SCAN) g_bstate[gtid] = 0ULL;
    }
    for (int i = threadIdx.x; i < 13 * 64; i += 256) W1s[i] = W1[i];
    if (threadIdx.x < 64) b1s[threadIdx.x] = b1[threadIdx.x];

    const int warp = threadIdx.x >> 5;
    const int lane = threadIdx.x & 31;
    const int v = blockIdx.x * 8 + warp;
    const int sub = lane & 3, grp = lane >> 2;   // 4 lanes/edge, 8 groups

    float acc[4] = {0, 0, 0, 0};
    if (grp == 0) {
        int2 raw = *(const int2*)(g_x0h + v * 16 + sub * 4);
        acch4(acc, H2(raw.x), H2(raw.y));
    }
    int beg = g_rowptr[v], end = g_rowptr[v + 1];
    for (int t = beg; t < end; t += 32) {
        int myc = g_col[t + lane];        // +64 pad makes this safe
        int2 r[4];
#pragma unroll
        for (int k = 0; k < 4; k++) {
            int src = grp + 8 * k;
            int c = __shfl_sync(FULL, myc, src);
            if (t + src >= end) c = ZROW;
            r[k] = *(const int2*)(g_x0h + c * 16 + sub * 4);
        }
        __half2 hx = __hadd2(__hadd2(H2(r[0].x), H2(r[1].x)),
                             __hadd2(H2(r[2].x), H2(r[3].x)));
        __half2 hy = __hadd2(__hadd2(H2(r[0].y), H2(r[1].y)),
                             __hadd2(H2(r[2].y), H2(r[3].y)));
        acch4(acc, hx, hy);
    }
#pragma unroll
    for (int off = 4; off <= 16; off <<= 1)
#pragma unroll
        for (int c = 0; c < 4; c++) acc[c] += __shfl_xor_sync(FULL, acc[c], off);
    if (lane < 4)
        *(float4*)&s_x[warp][lane * 4] = make_float4(acc[0], acc[1], acc[2], acc[3]);
    if (lane == 0) s_di[warp] = g_dinv[v];
    __syncthreads();

    // Phase B: warp w -> outputs [8w, 8w+8) for all 8 nodes
    const int n = lane >> 2, cc = lane & 3;
    const int j0 = 8 * warp + 2 * cc;
    float dx = 0.0f, dy = 0.0f;
#pragma unroll
    for (int k = 0; k < 13; k++) {
        float a = s_x[n][k];
        float2 w = *(const float2*)&W1s[k * 64 + j0];
        dx += a * w.x;
        dy += a * w.y;
    }
    float di = s_di[n];
    float zx = di * dx + b1s[j0];
    float zy = di * dy + b1s[j0 + 1];
    s_oh[n][4 * warp + cc] = __floats2half2_rn(di * fmaxf(zx, 0.0f),
                                               di * fmaxf(zy, 0.0f));
    __syncthreads();

    if (lane < 8) {
        __half2 u0 = s_oh[warp][4 * lane + 0];
        __half2 u1 = s_oh[warp][4 * lane + 1];
        __half2 u2 = s_oh[warp][4 * lane + 2];
        __half2 u3 = s_oh[warp][4 * lane + 3];
        int4 pack = make_int4(*(int*)&u0, *(int*)&u1, *(int*)&u2, *(int*)&u3);
        *reinterpret_cast<int4*>(g_x1h + v * 64 + lane * 8) = pack;
    }
}

// ---------------- 5. layer 2 (persistent) ----------------
// Phase A: 8 lanes/edge (int4), 32 edges/iter, shfl cols, 8-deep hadd2 tree.
__global__ void k_layer2(const float* __restrict__ W2,
                         const float* __restrict__ b2,
                         const float* __restrict__ W3) {
    __shared__ float W2s[64 * 64];
    __shared__ float b2s[64];
    __shared__ float W3s[64 * 10];
    __shared__ float s_agg[8][68];
    __shared__ float s_x2[8][68];
    __shared__ __half2 s_x1h[8][33];
    __shared__ float s_di[8];

    for (int i = threadIdx.x; i < 64 * 64; i += 256) W2s[i] = W2[i];
    if (threadIdx.x < 64) b2s[threadIdx.x] = b2[threadIdx.x];
    for (int i = threadIdx.x; i < 64 * 10; i += 256) W3s[i] = W3[i];

    const int warp = threadIdx.x >> 5;
    const int lane = threadIdx.x & 31;
    const int sub = lane & 7, grp = lane >> 3;   // 8 lanes/edge, 4 groups
    const int n = lane >> 2, cc = lane & 3;
    const int j0 = 8 * warp + 2 * cc;

    for (int gg = blockIdx.x; gg < NGRP; gg += PBLKS) {
        __syncthreads();
        const int v = gg * 8 + warp;

        float acc[8] = {0, 0, 0, 0, 0, 0, 0, 0};
        if (grp == 0) {
            const __half* self = g_x1h + v * 64 + sub * 8;
            int4 raw = *reinterpret_cast<const int4*>(self);
            acch(acc, H2(raw.x), H2(raw.y), H2(raw.z), H2(raw.w));
            s_x1h[warp][sub * 4 + 0] = H2(raw.x);
            s_x1h[warp][sub * 4 + 1] = H2(raw.y);
            s_x1h[warp][sub * 4 + 2] = H2(raw.z);
            s_x1h[warp][sub * 4 + 3] = H2(raw.w);
        }
        int beg = g_rowptr[v], end = g_rowptr[v + 1];
        for (int t = beg; t < end; t += 32) {
            int myc = g_col[t + lane];
            int4 r[8];
#pragma unroll
            for (int k = 0; k < 8; k++) {
                int src = grp + 4 * k;
                int c = __shfl_sync(FULL, myc, src);
                if (t + src >= end) c = ZROW;
                r[k] = *(const int4*)(g_x1h + c * 64 + sub * 8);
            }
            __half2 sx = __hadd2(
                __hadd2(__hadd2(H2(r[0].x), H2(r[1].x)), __hadd2(H2(r[2].x), H2(r[3].x))),
                __hadd2(__hadd2(H2(r[4].x), H2(r[5].x)), __hadd2(H2(r[6].x), H2(r[7].x))));
            __half2 sy = __hadd2(
                __hadd2(__hadd2(H2(r[0].y), H2(r[1].y)), __hadd2(H2(r[2].y), H2(r[3].y))),
                __hadd2(__hadd2(H2(r[4].y), H2(r[5].y)), __hadd2(H2(r[6].y), H2(r[7].y))));
            __half2 sz = __hadd2(
                __hadd2(__hadd2(H2(r[0].z), H2(r[1].z)), __hadd2(H2(r[2].z), H2(r[3].z))),
                __hadd2(__hadd2(H2(r[4].z), H2(r[5].z)), __hadd2(H2(r[6].z), H2(r[7].z))));
            __half2 sw = __hadd2(
                __hadd2(__hadd2(H2(r[0].w), H2(r[1].w)), __hadd2(H2(r[2].w), H2(r[3].w))),
                __hadd2(__hadd2(H2(r[4].w), H2(r[5].w)), __hadd2(H2(r[6].w), H2(r[7].w))));
            acch(acc, sx, sy, sz, sw);
        }
#pragma unroll
        for (int off = 8; off <= 16; off <<= 1)
#pragma unroll
            for (int c = 0; c < 8; c++) acc[c] += __shfl_xor_sync(FULL, acc[c], off);
        if (lane < 8) {
#pragma unroll
            for (int c = 0; c < 8; c++) s_agg[warp][sub * 8 + c] = acc[c];
        }
        if (lane == 0) s_di[warp] = g_dinv[v];
        __syncthreads();

        // Phase B: x2 = relu(di*(agg@W2)+b2) + x1
        float dx = 0.0f, dy = 0.0f;
#pragma unroll
        for (int k4 = 0; k4 < 16; k4++) {
            float4 a = *(const float4*)&s_agg[n][4 * k4];
            float2 w0 = *(const float2*)&W2s[(4 * k4 + 0) * 64 + j0];
            float2 w1 = *(const float2*)&W2s[(4 * k4 + 1) * 64 + j0];
            float2 w2 = *(const float2*)&W2s[(4 * k4 + 2) * 64 + j0];
            float2 w3 = *(const float2*)&W2s[(4 * k4 + 3) * 64 + j0];
            dx += a.x * w0.x + a.y * w1.x + a.z * w2.x + a.w * w3.x;
            dy += a.x * w0.y + a.y * w1.y + a.z * w2.y + a.w * w3.y;
        }
        float di = s_di[n];
        float zx = di * dx + b2s[j0];
        float zy = di * dy + b2s[j0 + 1];
        float rdeg = 1.0f / di;
        float2 r = __half22float2(s_x1h[n][4 * warp + cc]);
        s_x2[n][j0]     = fmaxf(zx, 0.0f) + r.x * rdeg;
        s_x2[n][j0 + 1] = fmaxf(zy, 0.0f) + r.y * rdeg;
        __syncthreads();

        // Phase C: 80 threads compute the 80 (node, class) dots; p' = di*p
        if (threadIdx.x < 80) {
            int n2 = threadIdx.x / 10;
            int j  = threadIdx.x - n2 * 10;
            float p = 0.0f;
#pragma unroll
            for (int k4 = 0; k4 < 16; k4++) {
                float4 a = *(const float4*)&s_x2[n2][4 * k4];
                p += a.x * W3s[(4 * k4 + 0) * 10 + j]
                   + a.y * W3s[(4 * k4 + 1) * 10 + j]
                   + a.z * W3s[(4 * k4 + 2) * 10 + j]
                   + a.w * W3s[(4 * k4 + 3) * 10 + j];
            }
            g_ph[(gg * 8 + n2) * 16 + j] = __float2half(s_di[n2] * p);
        }
    }
}

// ---------------- 6. layer 3: 32 edges/iter, shfl cols, tree hadd2 ----------------
__global__ void k_layer3(const float* __restrict__ b3, float* __restrict__ out) {
    __shared__ __align__(16) float sp[8][16];
    int warp = threadIdx.x >> 5;
    int v = blockIdx.x * 8 + warp;
    int lane = threadIdx.x & 31;
    int sub = lane & 3, grp = lane >> 2;   // 4 lanes/edge, 8 groups

    float acc[4] = {0, 0, 0, 0};
    if (grp == 0) {
        int2 raw = *(const int2*)(g_ph + v * 16 + sub * 4);
        acch4(acc, H2(raw.x), H2(raw.y));
    }
    int beg = g_rowptr[v], end = g_rowptr[v + 1];
    for (int t = beg; t < end; t += 32) {
        int myc = g_col[t + lane];
        int2 r[4];
#pragma unroll
        for (int k = 0; k < 4; k++) {
            int src = grp + 8 * k;
            int c = __shfl_sync(FULL, myc, src);
            if (t + src >= end) c = ZROW;
            r[k] = *(const int2*)(g_ph + c * 16 + sub * 4);
        }
        __half2 hx = __hadd2(__hadd2(H2(r[0].x), H2(r[1].x)),
                             __hadd2(H2(r[2].x), H2(r[3].x)));
        __half2 hy = __hadd2(__hadd2(H2(r[0].y), H2(r[1].y)),
                             __hadd2(H2(r[2].y), H2(r[3].y)));
        acch4(acc, hx, hy);
    }
#pragma unroll
    for (int off = 4; off <= 16; off <<= 1)
#pragma unroll
        for (int c = 0; c < 4; c++) acc[c] += __shfl_xor_sync(FULL, acc[c], off);

    if (lane < 4)
        *(float4*)&sp[warp][lane * 4] = make_float4(acc[0], acc[1], acc[2], acc[3]);
    __syncwarp();

    float di = g_dinv[v];
    float z = (lane < 10) ? di * sp[warp][lane] + b3[lane] : -INFINITY;
    float mx = z;
    for (int off = 16; off; off >>= 1) mx = fmaxf(mx, __shfl_xor_sync(FULL, mx, off));
    float ex = (lane < 10) ? expf(z - mx) : 0.0f;
    float s = ex;
    for (int off = 16; off; off >>= 1) s += __shfl_xor_sync(FULL, s, off);
    if (lane < 10) out[v * 10 + lane] = z - mx - logf(s);
}

extern "C" void kernel_launch(void* const* d_in, const int* in_sizes, int n_in,
                              void* d_out, int out_size) {
    const float* x  = (const float*)d_in[0];
    const int*   ei = (const int*)d_in[1];
    const float* W1 = (const float*)d_in[2];
    const float* b1 = (const float*)d_in[3];
    const float* W2 = (const float*)d_in[4];
    const float* b2 = (const float*)d_in[5];
    const float* W3 = (const float*)d_in[6];
    const float* b3 = (const float*)d_in[7];
    float* out = (float*)d_out;

    const int TB = 256;
    int hist4Blocks = (N_EDGES / 4 + TB - 1) / TB;
    int scat2Blocks = (N_EDGES / 2 + TB - 1) / TB;

    k_hist<<<hist4Blocks, TB>>>(ei);
    k_scanfused<<<NB_SCAN, TB>>>(x);
    k_scatter<<<scat2Blocks, TB>>>(ei);
    k_layer1<<<NGRP, TB>>>(W1, b1);
    k_layer2<<<PBLKS, TB>>>(W2, b2, W3);
    k_layer3<<<NGRP, TB>>>(b3, out);
}

// round 11
// speedup vs baseline: 1.0578x; 1.0578x over previous
#include <cuda_runtime.h>
#include <cuda_fp16.h>
#include <math.h>

#define N_NODES 100000
#define N_EDGES 1600000
#define FULL 0xffffffffu
#define NB_SCAN 391        // ceil(100000/256)
#define ZROW N_NODES       // index of the always-zero feature row
#define NGRP 12500         // node groups of 8
#define PBLKS 1184         // persistent blocks for layer2 (148 SMs * 8)

// ---- scratch (static device globals; zero at load; layer1 restores zeros) ----
__device__ int   g_count[N_NODES];
__device__ int   g_rowptr[N_NODES + 1];
__device__ float g_dinv[N_NODES];
__device__ int   g_col[N_EDGES + 64];                  // +64 pad: safe tail loads
__device__ unsigned long long g_bstate[NB_SCAN];
__device__ __align__(16) __half g_x0h[(N_NODES + 1) * 16];  // row ZROW stays 0
__device__ __align__(16) __half g_x1h[(N_NODES + 1) * 64];  // row ZROW stays 0
__device__ __align__(16) __half g_ph [(N_NODES + 1) * 16];  // row ZROW + pads stay 0

#define H2(x) (*(__half2*)&(x))

// ---------------- 1. histogram (g_count zero on entry) ----------------
__global__ void k_hist(const int* __restrict__ ei) {
    int e4 = blockIdx.x * blockDim.x + threadIdx.x;
    if (e4 < N_EDGES / 4) {
        int4 d = ((const int4*)(ei + N_EDGES))[e4];
        atomicAdd(&g_count[d.x], 1);
        atomicAdd(&g_count[d.y], 1);
        atomicAdd(&g_count[d.z], 1);
        atomicAdd(&g_count[d.w], 1);
    }
}

// ---------------- 2. fused scan: rowptr + dinv + cursor + padx ----------------
__global__ void k_scanfused(const float* __restrict__ x) {
    __shared__ int s[256];
    __shared__ int s_prefix;
    const int tid = threadIdx.x;
    const int bid = blockIdx.x;
    const int i = bid * 256 + tid;

    int c = (i < N_NODES) ? g_count[i] : 0;
    s[tid] = c;
    __syncthreads();
    for (int off = 1; off < 256; off <<= 1) {
        int t = (tid >= off) ? s[tid - off] : 0;
        __syncthreads();
        s[tid] += t;
        __syncthreads();
    }
    int total = s[255];

    if (tid == 0) {
        if (bid == 0) {
            s_prefix = 0;
            atomicExch(&g_bstate[0], (2ULL << 32) | (unsigned int)total);
        } else {
            atomicExch(&g_bstate[bid], (1ULL << 32) | (unsigned int)total);
            int pre = 0;
            for (int j = bid - 1; j >= 0; j--) {
                unsigned long long st;
                do {
                    st = *((volatile unsigned long long*)&g_bstate[j]);
                } while ((st >> 32) == 0ULL);
                pre += (int)(st & 0xffffffffULL);
                if ((st >> 32) == 2ULL) break;
            }
            s_prefix = pre;
            atomicExch(&g_bstate[bid], (2ULL << 32) | (unsigned int)(pre + total));
        }
    }
    __syncthreads();

    if (i < N_NODES) {
        int rp = s_prefix + s[tid] - c;
        g_rowptr[i] = rp;
        float di = rsqrtf((float)c + 1.0f);
        g_dinv[i] = di;
        g_count[i] = rp;                  // absolute cursor for scatter
        __half2* o = (__half2*)(g_x0h + i * 16);
#pragma unroll
        for (int q = 0; q < 8; q++) {
            float a = (2 * q < 13)     ? di * x[i * 13 + 2 * q]     : 0.0f;
            float b = (2 * q + 1 < 13) ? di * x[i * 13 + 2 * q + 1] : 0.0f;
            o[q] = __floats2half2_rn(a, b);
        }
    }
    if (i == 0) g_rowptr[N_NODES] = N_EDGES;
}

// ---------------- 3. scatter: 4 edges/thread via int4 ----------------
__global__ void k_scatter(const int* __restrict__ ei) {
    int e4 = blockIdx.x * blockDim.x + threadIdx.x;
    if (e4 < N_EDGES / 4) {
        int4 ss = ((const int4*)ei)[e4];
        int4 dd = ((const int4*)(ei + N_EDGES))[e4];
        int p0 = atomicAdd(&g_count[dd.x], 1);
        int p1 = atomicAdd(&g_count[dd.y], 1);
        int p2 = atomicAdd(&g_count[dd.z], 1);
        int p3 = atomicAdd(&g_count[dd.w], 1);
        g_col[p0] = ss.x;
        g_col[p1] = ss.y;
        g_col[p2] = ss.z;
        g_col[p3] = ss.w;
    }
}

// fp32 accumulate one int4 (8 halves)
__device__ __forceinline__ void acc8(float* acc, const __half* base) {
    int4 raw = *reinterpret_cast<const int4*>(base);
    float2 f0 = __half22float2(H2(raw.x));
    float2 f1 = __half22float2(H2(raw.y));
    float2 f2 = __half22float2(H2(raw.z));
    float2 f3 = __half22float2(H2(raw.w));
    acc[0] += f0.x; acc[1] += f0.y; acc[2] += f1.x; acc[3] += f1.y;
    acc[4] += f2.x; acc[5] += f2.y; acc[6] += f3.x; acc[7] += f3.y;
}

// fp32 accumulate 4 half2 partial sums
__device__ __forceinline__ void acch(float* acc, __half2 s0, __half2 s1,
                                     __half2 s2, __half2 s3) {
    float2 f0 = __half22float2(s0);
    float2 f1 = __half22float2(s1);
    float2 f2 = __half22float2(s2);
    float2 f3 = __half22float2(s3);
    acc[0] += f0.x; acc[1] += f0.y; acc[2] += f1.x; acc[3] += f1.y;
    acc[4] += f2.x; acc[5] += f2.y; acc[6] += f3.x; acc[7] += f3.y;
}

// fp32 accumulate 2 half2 partial sums (4 floats)
__device__ __forceinline__ void acch4(float* acc, __half2 s0, __half2 s1) {
    float2 f0 = __half22float2(s0);
    float2 f1 = __half22float2(s1);
    acc[0] += f0.x; acc[1] += f0.y; acc[2] += f1.x; acc[3] += f1.y;
}

// ---------------- 4. layer 1 (non-persistent; + zero restore) ----------------
// block = 8 warps = 8 nodes. Phase A: 4 lanes/edge (int2), 8 edge groups,
// 16 edges/pass, 12-shfl reduction. Phase B: redistributed GEMM 13->64.
__global__ void k_layer1(const float* __restrict__ W1,
                         const float* __restrict__ b1) {
    __shared__ float W1s[13 * 64];
    __shared__ float b1s[64];
    __shared__ float s_x[8][20];
    __shared__ float s_di[8];
    __shared__ __half2 s_oh[8][33];

    {
        int gtid = blockIdx.x * 256 + threadIdx.x;
        if (gtid < N_NODES) g_count[gtid] = 0;
        if (gtid < NB_SCAN) g_bstate[gtid] = 0ULL;
    }
    for (int i = threadIdx.x; i < 13 * 64; i += 256) W1s[i] = W1[i];
    if (threadIdx.x < 64) b1s[threadIdx.x] = b1[threadIdx.x];

    const int warp = threadIdx.x >> 5;
    const int lane = threadIdx.x & 31;
    const int v = blockIdx.x * 8 + warp;
    const int sub = lane & 3, grp = lane >> 2;   // 4 lanes/edge, 8 groups

    float acc[4] = {0, 0, 0, 0};
    if (grp == 0) {
        int2 raw = *(const int2*)(g_x0h + v * 16 + sub * 4);
        acch4(acc, H2(raw.x), H2(raw.y));
    }
    int beg = g_rowptr[v], end = g_rowptr[v + 1];
    for (int t = beg; t < end; t += 16) {
        int i0 = t + grp, i1 = i0 + 8;
        int c0 = (i0 < end) ? g_col[i0] : ZROW;
        int c1 = (i1 < end) ? g_col[i1] : ZROW;
        int2 r0 = *(const int2*)(g_x0h + c0 * 16 + sub * 4);
        int2 r1 = *(const int2*)(g_x0h + c1 * 16 + sub * 4);
        acch4(acc, __hadd2(H2(r0.x), H2(r1.x)), __hadd2(H2(r0.y), H2(r1.y)));
    }
#pragma unroll
    for (int off = 4; off <= 16; off <<= 1)
#pragma unroll
        for (int c = 0; c < 4; c++) acc[c] += __shfl_xor_sync(FULL, acc[c], off);
    if (lane < 4)
        *(float4*)&s_x[warp][lane * 4] = make_float4(acc[0], acc[1], acc[2], acc[3]);
    if (lane == 0) s_di[warp] = g_dinv[v];
    __syncthreads();

    // Phase B: warp w -> outputs [8w, 8w+8) for all 8 nodes
    const int n = lane >> 2, cc = lane & 3;
    const int j0 = 8 * warp + 2 * cc;
    float dx = 0.0f, dy = 0.0f;
#pragma unroll
    for (int k = 0; k < 13; k++) {
        float a = s_x[n][k];
        float2 w = *(const float2*)&W1s[k * 64 + j0];
        dx += a * w.x;
        dy += a * w.y;
    }
    float di = s_di[n];
    float zx = di * dx + b1s[j0];
    float zy = di * dy + b1s[j0 + 1];
    s_oh[n][4 * warp + cc] = __floats2half2_rn(di * fmaxf(zx, 0.0f),
                                               di * fmaxf(zy, 0.0f));
    __syncthreads();

    if (lane < 8) {
        __half2 u0 = s_oh[warp][4 * lane + 0];
        __half2 u1 = s_oh[warp][4 * lane + 1];
        __half2 u2 = s_oh[warp][4 * lane + 2];
        __half2 u3 = s_oh[warp][4 * lane + 3];
        int4 pack = make_int4(*(int*)&u0, *(int*)&u1, *(int*)&u2, *(int*)&u3);
        *reinterpret_cast<int4*>(g_x1h + v * 64 + lane * 8) = pack;
    }
}

// ---------------- 5. layer 2 (persistent; round-9 configuration) ----------------
__global__ void k_layer2(const float* __restrict__ W2,
                         const float* __restrict__ b2,
                         const float* __restrict__ W3) {
    __shared__ float W2s[64 * 64];
    __shared__ float b2s[64];
    __shared__ float W3s[64 * 10];
    __shared__ float s_agg[8][68];
    __shared__ float s_x2[8][68];
    __shared__ __half2 s_x1h[8][33];
    __shared__ float s_di[8];

    for (int i = threadIdx.x; i < 64 * 64; i += 256) W2s[i] = W2[i];
    if (threadIdx.x < 64) b2s[threadIdx.x] = b2[threadIdx.x];
    for (int i = threadIdx.x; i < 64 * 10; i += 256) W3s[i] = W3[i];

    const int warp = threadIdx.x >> 5;
    const int lane = threadIdx.x & 31;
    const int sub = lane & 7, grp = lane >> 3;   // 8 lanes/edge, 4 edges/pass
    const int n = lane >> 2, cc = lane & 3;
    const int j0 = 8 * warp + 2 * cc;

    for (int gg = blockIdx.x; gg < NGRP; gg += PBLKS) {
        __syncthreads();
        const int v = gg * 8 + warp;

        float acc[8] = {0, 0, 0, 0, 0, 0, 0, 0};
        if (grp == 0) {
            const __half* self = g_x1h + v * 64 + sub * 8;
            acc8(acc, self);
            int4 raw = *reinterpret_cast<const int4*>(self);
            s_x1h[warp][sub * 4 + 0] = H2(raw.x);
            s_x1h[warp][sub * 4 + 1] = H2(raw.y);
            s_x1h[warp][sub * 4 + 2] = H2(raw.z);
            s_x1h[warp][sub * 4 + 3] = H2(raw.w);
        }
        int beg = g_rowptr[v], end = g_rowptr[v + 1];
        for (int t = beg; t < end; t += 16) {
            int i0 = t + grp, i1 = i0 + 4, i2 = i0 + 8, i3 = i0 + 12;
            int c0 = (i0 < end) ? g_col[i0] : ZROW;
            int c1 = (i1 < end) ? g_col[i1] : ZROW;
            int c2 = (i2 < end) ? g_col[i2] : ZROW;
            int c3 = (i3 < end) ? g_col[i3] : ZROW;
            int4 r0 = *(const int4*)(g_x1h + c0 * 64 + sub * 8);
            int4 r1 = *(const int4*)(g_x1h + c1 * 64 + sub * 8);
            int4 r2 = *(const int4*)(g_x1h + c2 * 64 + sub * 8);
            int4 r3 = *(const int4*)(g_x1h + c3 * 64 + sub * 8);
            acch(acc,
                 __hadd2(__hadd2(H2(r0.x), H2(r1.x)), __hadd2(H2(r2.x), H2(r3.x))),
                 __hadd2(__hadd2(H2(r0.y), H2(r1.y)), __hadd2(H2(r2.y), H2(r3.y))),
                 __hadd2(__hadd2(H2(r0.z), H2(r1.z)), __hadd2(H2(r2.z), H2(r3.z))),
                 __hadd2(__hadd2(H2(r0.w), H2(r1.w)), __hadd2(H2(r2.w), H2(r3.w))));
        }
#pragma unroll
        for (int off = 8; off <= 16; off <<= 1)
#pragma unroll
            for (int c = 0; c < 8; c++) acc[c] += __shfl_xor_sync(FULL, acc[c], off);
        if (lane < 8) {
#pragma unroll
            for (int c = 0; c < 8; c++) s_agg[warp][sub * 8 + c] = acc[c];
        }
        if (lane == 0) s_di[warp] = g_dinv[v];
        __syncthreads();

        // Phase B: x2 = relu(di*(agg@W2)+b2) + x1
        float dx = 0.0f, dy = 0.0f;
#pragma unroll
        for (int k4 = 0; k4 < 16; k4++) {
            float4 a = *(const float4*)&s_agg[n][4 * k4];
            float2 w0 = *(const float2*)&W2s[(4 * k4 + 0) * 64 + j0];
            float2 w1 = *(const float2*)&W2s[(4 * k4 + 1) * 64 + j0];
            float2 w2 = *(const float2*)&W2s[(4 * k4 + 2) * 64 + j0];
            float2 w3 = *(const float2*)&W2s[(4 * k4 + 3) * 64 + j0];
            dx += a.x * w0.x + a.y * w1.x + a.z * w2.x + a.w * w3.x;
            dy += a.x * w0.y + a.y * w1.y + a.z * w2.y + a.w * w3.y;
        }
        float di = s_di[n];
        float zx = di * dx + b2s[j0];
        float zy = di * dy + b2s[j0 + 1];
        float rdeg = 1.0f / di;
        float2 r = __half22float2(s_x1h[n][4 * warp + cc]);
        s_x2[n][j0]     = fmaxf(zx, 0.0f) + r.x * rdeg;
        s_x2[n][j0 + 1] = fmaxf(zy, 0.0f) + r.y * rdeg;
        __syncthreads();

        // Phase C: 80 threads compute the 80 (node, class) dots; p' = di*p
        if (threadIdx.x < 80) {
            int n2 = threadIdx.x / 10;
            int j  = threadIdx.x - n2 * 10;
            float p = 0.0f;
#pragma unroll
            for (int k4 = 0; k4 < 16; k4++) {
                float4 a = *(const float4*)&s_x2[n2][4 * k4];
                p += a.x * W3s[(4 * k4 + 0) * 10 + j]
                   + a.y * W3s[(4 * k4 + 1) * 10 + j]
                   + a.z * W3s[(4 * k4 + 2) * 10 + j]
                   + a.w * W3s[(4 * k4 + 3) * 10 + j];
            }
            g_ph[(gg * 8 + n2) * 16 + j] = __float2half(s_di[n2] * p);
        }
    }
}

// ---------------- 6. layer 3: 4 lanes/edge, 12-shfl reduction ----------------
__global__ void k_layer3(const float* __restrict__ b3, float* __restrict__ out) {
    __shared__ __align__(16) float sp[8][16];
    int warp = threadIdx.x >> 5;
    int v = blockIdx.x * 8 + warp;
    int lane = threadIdx.x & 31;
    int sub = lane & 3, grp = lane >> 2;   // 4 lanes/edge, 8 groups

    float acc[4] = {0, 0, 0, 0};
    if (grp == 0) {
        int2 raw = *(const int2*)(g_ph + v * 16 + sub * 4);
        acch4(acc, H2(raw.x), H2(raw.y));
    }
    int beg = g_rowptr[v], end = g_rowptr[v + 1];
    for (int t = beg; t < end; t += 16) {
        int i0 = t + grp, i1 = i0 + 8;
        int c0 = (i0 < end) ? g_col[i0] : ZROW;
        int c1 = (i1 < end) ? g_col[i1] : ZROW;
        int2 r0 = *(const int2*)(g_ph + c0 * 16 + sub * 4);
        int2 r1 = *(const int2*)(g_ph + c1 * 16 + sub * 4);
        acch4(acc, __hadd2(H2(r0.x), H2(r1.x)), __hadd2(H2(r0.y), H2(r1.y)));
    }
#pragma unroll
    for (int off = 4; off <= 16; off <<= 1)
#pragma unroll
        for (int c = 0; c < 4; c++) acc[c] += __shfl_xor_sync(FULL, acc[c], off);

    if (lane < 4)
        *(float4*)&sp[warp][lane * 4] = make_float4(acc[0], acc[1], acc[2], acc[3]);
    __syncwarp();

    float di = g_dinv[v];
    float z = (lane < 10) ? di * sp[warp][lane] + b3[lane] : -INFINITY;
    float mx = z;
    for (int off = 16; off; off >>= 1) mx = fmaxf(mx, __shfl_xor_sync(FULL, mx, off));
    float ex = (lane < 10) ? expf(z - mx) : 0.0f;
    float s = ex;
    for (int off = 16; off; off >>= 1) s += __shfl_xor_sync(FULL, s, off);
    if (lane < 10) out[v * 10 + lane] = z - mx - logf(s);
}

extern "C" void kernel_launch(void* const* d_in, const int* in_sizes, int n_in,
                              void* d_out, int out_size) {
    const float* x  = (const float*)d_in[0];
    const int*   ei = (const int*)d_in[1];
    const float* W1 = (const float*)d_in[2];
    const float* b1 = (const float*)d_in[3];
    const float* W2 = (const float*)d_in[4];
    const float* b2 = (const float*)d_in[5];
    const float* W3 = (const float*)d_in[6];
    const float* b3 = (const float*)d_in[7];
    float* out = (float*)d_out;

    const int TB = 256;
    int hist4Blocks = (N_EDGES / 4 + TB - 1) / TB;
    int scat4Blocks = (N_EDGES / 4 + TB - 1) / TB;

    k_hist<<<hist4Blocks, TB>>>(ei);
    k_scanfused<<<NB_SCAN, TB>>>(x);
    k_scatter<<<scat4Blocks, TB>>>(ei);
    k_layer1<<<NGRP, TB>>>(W1, b1);
    k_layer2<<<PBLKS, TB>>>(W2, b2, W3);
    k_layer3<<<NGRP, TB>>>(b3, out);
}

// round 13
// speedup vs baseline: 1.4148x; 1.3375x over previous
#include <cuda_runtime.h>
#include <cuda_fp16.h>
#include <math.h>
#include <stdint.h>

#define N_NODES 100000
#define N_EDGES 1600000
#define FULL 0xffffffffu
#define NB_SCAN 391        // ceil(100000/256)
#define ZROW N_NODES       // index of the always-zero feature row
#define NGRP 12500         // node groups of 8
#define MTILES 782         // ceil(100000/128) gemm2 blocks
#define N_PAD (MTILES * 128)

// ---- scratch (static device globals; zero at load; layer1 restores zeros) ----
__device__ int   g_count[N_NODES];
__device__ int   g_rowptr[N_NODES + 1];
__device__ float g_dinv[N_NODES];
__device__ int   g_col[N_EDGES + 64];                  // +64 pad: safe tail loads
__device__ unsigned long long g_bstate[NB_SCAN];
__device__ __align__(16) __half g_x0h[(N_NODES + 1) * 16];   // row ZROW stays 0
__device__ __align__(16) __half g_x1h[(N_NODES + 1) * 64];   // row ZROW stays 0
__device__ __align__(16) __half g_aggh[N_PAD * 64];          // di*agg(x1'); pad rows stay 0
__device__ __align__(16) __half g_ph [(N_NODES + 1) * 16];   // row ZROW + pads stay 0

#define H2(x) (*(__half2*)&(x))

__device__ __forceinline__ unsigned int smem_u32(const void* p) {
    unsigned int r;
    asm("{ .reg .u64 t; cvta.to.shared.u64 t, %1; cvt.u32.u64 %0, t; }"
        : "=r"(r) : "l"(p));
    return r;
}

__device__ __forceinline__ void mma_16816(float* c, unsigned int a0, unsigned int a1,
                                          unsigned int a2, unsigned int a3,
                                          unsigned int b0, unsigned int b1) {
    asm volatile(
        "mma.sync.aligned.m16n8k16.row.col.f32.f16.f16.f32 "
        "{%0,%1,%2,%3}, {%4,%5,%6,%7}, {%8,%9}, {%0,%1,%2,%3};"
        : "+f"(c[0]), "+f"(c[1]), "+f"(c[2]), "+f"(c[3])
        : "r"(a0), "r"(a1), "r"(a2), "r"(a3), "r"(b0), "r"(b1));
}

// ---------------- 1. histogram (g_count zero on entry) ----------------
__global__ void k_hist(const int* __restrict__ ei) {
    int e4 = blockIdx.x * blockDim.x + threadIdx.x;
    if (e4 < N_EDGES / 4) {
        int4 d = ((const int4*)(ei + N_EDGES))[e4];
        atomicAdd(&g_count[d.x], 1);
        atomicAdd(&g_count[d.y], 1);
        atomicAdd(&g_count[d.z], 1);
        atomicAdd(&g_count[d.w], 1);
    }
}

// ---------------- 2. fused scan: rowptr + dinv + cursor + padx ----------------
__global__ void k_scanfused(const float* __restrict__ x) {
    __shared__ int s[256];
    __shared__ int s_prefix;
    const int tid = threadIdx.x;
    const int bid = blockIdx.x;
    const int i = bid * 256 + tid;

    int c = (i < N_NODES) ? g_count[i] : 0;
    s[tid] = c;
    __syncthreads();
    for (int off = 1; off < 256; off <<= 1) {
        int t = (tid >= off) ? s[tid - off] : 0;
        __syncthreads();
        s[tid] += t;
        __syncthreads();
    }
    int total = s[255];

    if (tid == 0) {
        if (bid == 0) {
            s_prefix = 0;
            atomicExch(&g_bstate[0], (2ULL << 32) | (unsigned int)total);
        } else {
            atomicExch(&g_bstate[bid], (1ULL << 32) | (unsigned int)total);
            int pre = 0;
            for (int j = bid - 1; j >= 0; j--) {
                unsigned long long st;
                do {
                    st = *((volatile unsigned long long*)&g_bstate[j]);
                } while ((st >> 32) == 0ULL);
                pre += (int)(st & 0xffffffffULL);
                if ((st >> 32) == 2ULL) break;
            }
            s_prefix = pre;
            atomicExch(&g_bstate[bid], (2ULL << 32) | (unsigned int)(pre + total));
        }
    }
    __syncthreads();

    if (i < N_NODES) {
        int rp = s_prefix + s[tid] - c;
        g_rowptr[i] = rp;
        float di = rsqrtf((float)c + 1.0f);
        g_dinv[i] = di;
        g_count[i] = rp;                  // absolute cursor for scatter
        __half2* o = (__half2*)(g_x0h + i * 16);
#pragma unroll
        for (int q = 0; q < 8; q++) {
            float a = (2 * q < 13)     ? di * x[i * 13 + 2 * q]     : 0.0f;
            float b = (2 * q + 1 < 13) ? di * x[i * 13 + 2 * q + 1] : 0.0f;
            o[q] = __floats2half2_rn(a, b);
        }
    }
    if (i == 0) g_rowptr[N_NODES] = N_EDGES;
}

// ---------------- 3. scatter: 4 edges/thread via int4 ----------------
__global__ void k_scatter(const int* __restrict__ ei) {
    int e4 = blockIdx.x * blockDim.x + threadIdx.x;
    if (e4 < N_EDGES / 4) {
        int4 ss = ((const int4*)ei)[e4];
        int4 dd = ((const int4*)(ei + N_EDGES))[e4];
        int p0 = atomicAdd(&g_count[dd.x], 1);
        int p1 = atomicAdd(&g_count[dd.y], 1);
        int p2 = atomicAdd(&g_count[dd.z], 1);
        int p3 = atomicAdd(&g_count[dd.w], 1);
        g_col[p0] = ss.x;
        g_col[p1] = ss.y;
        g_col[p2] = ss.z;
        g_col[p3] = ss.w;
    }
}

// fp32 accumulate one int4 (8 halves)
__device__ __forceinline__ void acc8(float* acc, const __half* base) {
    int4 raw = *reinterpret_cast<const int4*>(base);
    float2 f0 = __half22float2(H2(raw.x));
    float2 f1 = __half22float2(H2(raw.y));
    float2 f2 = __half22float2(H2(raw.z));
    float2 f3 = __half22float2(H2(raw.w));
    acc[0] += f0.x; acc[1] += f0.y; acc[2] += f1.x; acc[3] += f1.y;
    acc[4] += f2.x; acc[5] += f2.y; acc[6] += f3.x; acc[7] += f3.y;
}

// fp32 accumulate 4 half2 partial sums
__device__ __forceinline__ void acch(float* acc, __half2 s0, __half2 s1,
                                     __half2 s2, __half2 s3) {
    float2 f0 = __half22float2(s0);
    float2 f1 = __half22float2(s1);
    float2 f2 = __half22float2(s2);
    float2 f3 = __half22float2(s3);
    acc[0] += f0.x; acc[1] += f0.y; acc[2] += f1.x; acc[3] += f1.y;
    acc[4] += f2.x; acc[5] += f2.y; acc[6] += f3.x; acc[7] += f3.y;
}

// fp32 accumulate 2 half2 partial sums (4 floats)
__device__ __forceinline__ void acch4(float* acc, __half2 s0, __half2 s1) {
    float2 f0 = __half22float2(s0);
    float2 f1 = __half22float2(s1);
    acc[0] += f0.x; acc[1] += f0.y; acc[2] += f1.x; acc[3] += f1.y;
}

// ---------------- 4. layer 1 (non-persistent; + zero restore) ----------------
__global__ void k_layer1(const float* __restrict__ W1,
                         const float* __restrict__ b1) {
    __shared__ float W1s[13 * 64];
    __shared__ float b1s[64];
    __shared__ float s_x[8][20];
    __shared__ float s_di[8];
    __shared__ __half2 s_oh[8][33];

    {
        int gtid = blockIdx.x * 256 + threadIdx.x;
        if (gtid < N_NODES) g_count[gtid] = 0;
        if (gtid < NB_SCAN) g_bstate[gtid] = 0ULL;
    }
    for (int i = threadIdx.x; i < 13 * 64; i += 256) W1s[i] = W1[i];
    if (threadIdx.x < 64) b1s[threadIdx.x] = b1[threadIdx.x];

    const int warp = threadIdx.x >> 5;
    const int lane = threadIdx.x & 31;
    const int v = blockIdx.x * 8 + warp;
    const int sub = lane & 3, grp = lane >> 2;   // 4 lanes/edge, 8 groups

    float acc[4] = {0, 0, 0, 0};
    if (grp == 0) {
        int2 raw = *(const int2*)(g_x0h + v * 16 + sub * 4);
        acch4(acc, H2(raw.x), H2(raw.y));
    }
    int beg = g_rowptr[v], end = g_rowptr[v + 1];
    for (int t = beg; t < end; t += 16) {
        int i0 = t + grp, i1 = i0 + 8;
        int c0 = (i0 < end) ? g_col[i0] : ZROW;
        int c1 = (i1 < end) ? g_col[i1] : ZROW;
        int2 r0 = *(const int2*)(g_x0h + c0 * 16 + sub * 4);
        int2 r1 = *(const int2*)(g_x0h + c1 * 16 + sub * 4);
        acch4(acc, __hadd2(H2(r0.x), H2(r1.x)), __hadd2(H2(r0.y), H2(r1.y)));
    }
#pragma unroll
    for (int off = 4; off <= 16; off <<= 1)
#pragma unroll
        for (int c = 0; c < 4; c++) acc[c] += __shfl_xor_sync(FULL, acc[c], off);
    if (lane < 4)
        *(float4*)&s_x[warp][lane * 4] = make_float4(acc[0], acc[1], acc[2], acc[3]);
    if (lane == 0) s_di[warp] = g_dinv[v];
    __syncthreads();

    // Phase B: warp w -> outputs [8w, 8w+8) for all 8 nodes
    const int n = lane >> 2, cc = lane & 3;
    const int j0 = 8 * warp + 2 * cc;
    float dx = 0.0f, dy = 0.0f;
#pragma unroll
    for (int k = 0; k < 13; k++) {
        float a = s_x[n][k];
        float2 w = *(const float2*)&W1s[k * 64 + j0];
        dx += a * w.x;
        dy += a * w.y;
    }
    float di = s_di[n];
    float zx = di * dx + b1s[j0];
    float zy = di * dy + b1s[j0 + 1];
    s_oh[n][4 * warp + cc] = __floats2half2_rn(di * fmaxf(zx, 0.0f),
                                               di * fmaxf(zy, 0.0f));
    __syncthreads();

    if (lane < 8) {
        __half2 u0 = s_oh[warp][4 * lane + 0];
        __half2 u1 = s_oh[warp][4 * lane + 1];
        __half2 u2 = s_oh[warp][4 * lane + 2];
        __half2 u3 = s_oh[warp][4 * lane + 3];
        int4 pack = make_int4(*(int*)&u0, *(int*)&u1, *(int*)&u2, *(int*)&u3);
        *reinterpret_cast<int4*>(g_x1h + v * 64 + lane * 8) = pack;
    }
}

// ---------------- 5a. layer 2 aggregation: g_aggh[v] = di * agg(x1')[v] ----------------
__global__ void k_agg2() {
    const int warp = threadIdx.x >> 5;
    const int lane = threadIdx.x & 31;
    const int v = blockIdx.x * 8 + warp;
    const int sub = lane & 7, grp = lane >> 3;   // 8 lanes/edge, 4 edges/pass

    float acc[8] = {0, 0, 0, 0, 0, 0, 0, 0};
    if (grp == 0) acc8(acc, g_x1h + v * 64 + sub * 8);   // self term

    int beg = g_rowptr[v], end = g_rowptr[v + 1];
    for (int t = beg; t < end; t += 16) {
        int i0 = t + grp, i1 = i0 + 4, i2 = i0 + 8, i3 = i0 + 12;
        int c0 = (i0 < end) ? g_col[i0] : ZROW;
        int c1 = (i1 < end) ? g_col[i1] : ZROW;
        int c2 = (i2 < end) ? g_col[i2] : ZROW;
        int c3 = (i3 < end) ? g_col[i3] : ZROW;
        int4 r0 = *(const int4*)(g_x1h + c0 * 64 + sub * 8);
        int4 r1 = *(const int4*)(g_x1h + c1 * 64 + sub * 8);
        int4 r2 = *(const int4*)(g_x1h + c2 * 64 + sub * 8);
        int4 r3 = *(const int4*)(g_x1h + c3 * 64 + sub * 8);
        acch(acc,
             __hadd2(__hadd2(H2(r0.x), H2(r1.x)), __hadd2(H2(r2.x), H2(r3.x))),
             __hadd2(__hadd2(H2(r0.y), H2(r1.y)), __hadd2(H2(r2.y), H2(r3.y))),
             __hadd2(__hadd2(H2(r0.z), H2(r1.z)), __hadd2(H2(r2.z), H2(r3.z))),
             __hadd2(__hadd2(H2(r0.w), H2(r1.w)), __hadd2(H2(r2.w), H2(r3.w))));
    }
#pragma unroll
    for (int off = 8; off <= 16; off <<= 1)
#pragma unroll
        for (int c = 0; c < 8; c++) acc[c] += __shfl_xor_sync(FULL, acc[c], off);

    if (lane < 8) {                         // sub == lane here
        float di = g_dinv[v];
        __half2 h0 = __floats2half2_rn(di * acc[0], di * acc[1]);
        __half2 h1 = __floats2half2_rn(di * acc[2], di * acc[3]);
        __half2 h2 = __floats2half2_rn(di * acc[4], di * acc[5]);
        __half2 h3 = __floats2half2_rn(di * acc[6], di * acc[7]);
        int4 pack = make_int4(*(int*)&h0, *(int*)&h1, *(int*)&h2, *(int*)&h3);
        *reinterpret_cast<int4*>(g_aggh + v * 64 + lane * 8) = pack;
    }
}

// ---------------- 5b. layer 2 GEMM (tensor cores) + epilogue + projection ----------------
// block = 128 nodes, 8 warps; warp w computes rows [16w,16w+16) x 64 via mma.m16n8k16.
// x2 = relu(A@W2 + b2) + x1 ; p' = di * (x2 @ W3) -> g_ph
__global__ void k_gemm2(const float* __restrict__ W2,
                        const float* __restrict__ b2,
                        const float* __restrict__ W3) {
    __shared__ __align__(16) __half sA[128 * 72];   // agg tile, then x2 tile
    __shared__ __align__(16) __half sB[64 * 72];    // W2 fp16
    __shared__ float sW3[64 * 10];
    __shared__ float sB2[64];
    __shared__ float sDi[128];

    const int tid = threadIdx.x;
    const int base = blockIdx.x * 128;

    for (int idx = tid; idx < 128 * 8; idx += 256) {      // A tile (int4 chunks)
        int row = idx >> 3, c8 = idx & 7;
        *(int4*)&sA[row * 72 + c8 * 8] =
            *(const int4*)&g_aggh[(base + row) * 64 + c8 * 8];
    }
    for (int idx = tid; idx < 64 * 32; idx += 256) {      // W2 -> fp16
        int row = idx >> 5, c2 = idx & 31;
        float2 w = *(const float2*)&W2[row * 64 + c2 * 2];
        *(__half2*)&sB[row * 72 + c2 * 2] = __floats2half2_rn(w.x, w.y);
    }
    for (int i = tid; i < 640; i += 256) sW3[i] = W3[i];
    if (tid < 64) sB2[tid] = b2[tid];
    if (tid < 128) {
        int node = base + tid;
        sDi[tid] = (node < N_NODES) ? g_dinv[node] : 1.0f;
    }
    __syncthreads();

    const int warp = tid >> 5, lane = tid & 31;
    const int m0 = warp * 16;
    const unsigned int sa_base = smem_u32(sA);
    const unsigned int sb_base = smem_u32(sB);
    const unsigned int a_off = ((m0 + (lane & 15)) * 72 + ((lane >> 4) << 3)) * 2;
    const unsigned int b_r = (lane & 15);
    const unsigned int b_c = ((lane >> 4) << 3);

    float c[32];
#pragma unroll
    for (int i = 0; i < 32; i++) c[i] = 0.0f;

#pragma unroll
    for (int kc = 0; kc < 4; kc++) {
        const int kk = kc * 16;
        unsigned int a0, a1, a2, a3;
        unsigned int aaddr = sa_base + a_off + kk * 2;
        asm volatile("ldmatrix.sync.aligned.m8n8.x4.shared.b16 {%0,%1,%2,%3}, [%4];"
                     : "=r"(a0), "=r"(a1), "=r"(a2), "=r"(a3) : "r"(aaddr));
#pragma unroll
        for (int jt = 0; jt < 4; jt++) {
            const int j0 = jt * 16;
            unsigned int b0, b1, b2r, b3;
            unsigned int baddr = sb_base + (((kk + b_r) * 72) + j0 + b_c) * 2;
            asm volatile("ldmatrix.sync.aligned.m8n8.x4.trans.shared.b16 {%0,%1,%2,%3}, [%4];"
                         : "=r"(b0), "=r"(b1), "=r"(b2r), "=r"(b3) : "r"(baddr));
            mma_16816(&c[(2 * jt) * 4],     a0, a1, a2, a3, b0, b1);
            mma_16816(&c[(2 * jt + 1) * 4], a0, a1, a2, a3, b2r, b3);
        }
    }

    // Epilogue (warp-local rows): x2 = relu(c + b2) + x1 ; write fp16 into sA
    {
        const int g = lane >> 2;           // 0..7
        const int colp = 2 * (lane & 3);   // 0,2,4,6
        const int rowA = m0 + g, rowB = m0 + g + 8;
        const int nodeA = base + rowA, nodeB = base + rowB;
        const float rdA = 1.0f / sDi[rowA];
        const float rdB = 1.0f / sDi[rowB];
        const int ncA = (nodeA < N_NODES) ? nodeA : ZROW;
        const int ncB = (nodeB < N_NODES) ? nodeB : ZROW;
#pragma unroll
        for (int nt = 0; nt < 8; nt++) {
            const int j = nt * 8 + colp;
            float* cp = &c[nt * 4];
            float2 rA = __half22float2(*(const __half2*)&g_x1h[ncA * 64 + j]);
            float2 rB = __half22float2(*(const __half2*)&g_x1h[ncB * 64 + j]);
            float xA0 = fmaxf(cp[0] + sB2[j],     0.0f) + rA.x * rdA;
            float xA1 = fmaxf(cp[1] + sB2[j + 1], 0.0f) + rA.y * rdA;
            float xB0 = fmaxf(cp[2] + sB2[j],     0.0f) + rB.x * rdB;
            float xB1 = fmaxf(cp[3] + sB2[j + 1], 0.0f) + rB.y * rdB;
            *(__half2*)&sA[rowA * 72 + j] = __floats2half2_rn(xA0, xA1);
            *(__half2*)&sA[rowB * 72 + j] = __floats2half2_rn(xB0, xB1);
        }
    }
    __syncthreads();

    // Projection: 128 nodes x 10 classes; p' = di * (x2 @ W3)
    for (int ii = tid; ii < 1280; ii += 256) {
        const int rl = ii / 10, j = ii - rl * 10;
        const int node = base + rl;
        if (node < N_NODES) {
            float p = 0.0f;
#pragma unroll
            for (int k2 = 0; k2 < 32; k2++) {
                float2 a = __half22float2(*(const __half2*)&sA[rl * 72 + 2 * k2]);
                p += a.x * sW3[(2 * k2) * 10 + j] + a.y * sW3[(2 * k2 + 1) * 10 + j];
            }
            g_ph[node * 16 + j] = __float2half(sDi[rl] * p);
        }
    }
}

// ---------------- 6. layer 3: 4 lanes/edge, 12-shfl reduction ----------------
__global__ void k_layer3(const float* __restrict__ b3, float* __restrict__ out) {
    __shared__ __align__(16) float sp[8][16];
    int warp = threadIdx.x >> 5;
    int v = blockIdx.x * 8 + warp;
    int lane = threadIdx.x & 31;
    int sub = lane & 3, grp = lane >> 2;   // 4 lanes/edge, 8 groups

    float acc[4] = {0, 0, 0, 0};
    if (grp == 0) {
        int2 raw = *(const int2*)(g_ph + v * 16 + sub * 4);
        acch4(acc, H2(raw.x), H2(raw.y));
    }
    int beg = g_rowptr[v], end = g_rowptr[v + 1];
    for (int t = beg; t < end; t += 16) {
        int i0 = t + grp, i1 = i0 + 8;
        int c0 = (i0 < end) ? g_col[i0] : ZROW;
        int c1 = (i1 < end) ? g_col[i1] : ZROW;
        int2 r0 = *(const int2*)(g_ph + c0 * 16 + sub * 4);
        int2 r1 = *(const int2*)(g_ph + c1 * 16 + sub * 4);
        acch4(acc, __hadd2(H2(r0.x), H2(r1.x)), __hadd2(H2(r0.y), H2(r1.y)));
    }
#pragma unroll
    for (int off = 4; off <= 16; off <<= 1)
#pragma unroll
        for (int c = 0; c < 4; c++) acc[c] += __shfl_xor_sync(FULL, acc[c], off);

    if (lane < 4)
        *(float4*)&sp[warp][lane * 4] = make_float4(acc[0], acc[1], acc[2], acc[3]);
    __syncwarp();

    float di = g_dinv[v];
    float z = (lane < 10) ? di * sp[warp][lane] + b3[lane] : -INFINITY;
    float mx = z;
    for (int off = 16; off; off >>= 1) mx = fmaxf(mx, __shfl_xor_sync(FULL, mx, off));
    float ex = (lane < 10) ? expf(z - mx) : 0.0f;
    float s = ex;
    for (int off = 16; off; off >>= 1) s += __shfl_xor_sync(FULL, s, off);
    if (lane < 10) out[v * 10 + lane] = z - mx - logf(s);
}

extern "C" void kernel_launch(void* const* d_in, const int* in_sizes, int n_in,
                              void* d_out, int out_size) {
    const float* x  = (const float*)d_in[0];
    const int*   ei = (const int*)d_in[1];
    const float* W1 = (const float*)d_in[2];
    const float* b1 = (const float*)d_in[3];
    const float* W2 = (const float*)d_in[4];
    const float* b2 = (const float*)d_in[5];
    const float* W3 = (const float*)d_in[6];
    const float* b3 = (const float*)d_in[7];
    float* out = (float*)d_out;

    const int TB = 256;
    int hist4Blocks = (N_EDGES / 4 + TB - 1) / TB;
    int scat4Blocks = (N_EDGES / 4 + TB - 1) / TB;

    k_hist<<<hist4Blocks, TB>>>(ei);
    k_scanfused<<<NB_SCAN, TB>>>(x);
    k_scatter<<<scat4Blocks, TB>>>(ei);
    k_layer1<<<NGRP, TB>>>(W1, b1);
    k_agg2<<<NGRP, TB>>>();
    k_gemm2<<<MTILES, TB>>>(W2, b2, W3);
    k_layer3<<<NGRP, TB>>>(b3, out);
}

// round 14
// speedup vs baseline: 1.6404x; 1.1594x over previous
#include <cuda_runtime.h>
#include <cuda_fp16.h>
#include <math.h>
#include <stdint.h>

#define N_NODES 100000
#define N_EDGES 1600000
#define FULL 0xffffffffu
#define NB_SCAN 391        // ceil(100000/256)
#define ZROW N_NODES       // index of the always-zero feature row
#define NGRP 12500         // node groups of 8 (agg2)
#define NGRP16 6250        // node groups of 16 (agg1x / layer3)
#define MTILES 782         // ceil(100000/128) gemm blocks
#define N_PAD (MTILES * 128)

// ---- scratch (static device globals; zero at load; gemm1 restores zeros) ----
__device__ int   g_count[N_NODES];
__device__ int   g_rowptr[N_NODES + 1];
__device__ float g_dinv[N_NODES];
__device__ int   g_col[N_EDGES + 64];                  // +64 pad: safe tail loads
__device__ unsigned long long g_bstate[NB_SCAN];
__device__ __align__(16) __half g_x0h[(N_NODES + 1) * 16];   // di*x; row ZROW stays 0
__device__ __align__(16) __half g_agg0h[N_PAD * 16];         // di*agg(x0'); pads stay 0
__device__ __align__(16) __half g_x1h[(N_NODES + 1) * 64];   // di*x1; row ZROW stays 0
__device__ __align__(16) __half g_aggh[N_PAD * 64];          // di*agg(x1'); pads stay 0
__device__ __align__(16) __half g_ph [(N_NODES + 1) * 16];   // di*p; row ZROW + pads stay 0

#define H2(x) (*(__half2*)&(x))

__device__ __forceinline__ unsigned int smem_u32(const void* p) {
    unsigned int r;
    asm("{ .reg .u64 t; cvta.to.shared.u64 t, %1; cvt.u32.u64 %0, t; }"
        : "=r"(r) : "l"(p));
    return r;
}

__device__ __forceinline__ void mma_16816(float* c, unsigned int a0, unsigned int a1,
                                          unsigned int a2, unsigned int a3,
                                          unsigned int b0, unsigned int b1) {
    asm volatile(
        "mma.sync.aligned.m16n8k16.row.col.f32.f16.f16.f32 "
        "{%0,%1,%2,%3}, {%4,%5,%6,%7}, {%8,%9}, {%0,%1,%2,%3};"
        : "+f"(c[0]), "+f"(c[1]), "+f"(c[2]), "+f"(c[3])
        : "r"(a0), "r"(a1), "r"(a2), "r"(a3), "r"(b0), "r"(b1));
}

// ---------------- 1. histogram (g_count zero on entry) ----------------
__global__ void k_hist(const int* __restrict__ ei) {
    int e4 = blockIdx.x * blockDim.x + threadIdx.x;
    if (e4 < N_EDGES / 4) {
        int4 d = ((const int4*)(ei + N_EDGES))[e4];
        atomicAdd(&g_count[d.x], 1);
        atomicAdd(&g_count[d.y], 1);
        atomicAdd(&g_count[d.z], 1);
        atomicAdd(&g_count[d.w], 1);
    }
}

// ---------------- 2. fused scan: rowptr + dinv + cursor + padx ----------------
__global__ void k_scanfused(const float* __restrict__ x) {
    __shared__ int s[256];
    __shared__ int s_prefix;
    const int tid = threadIdx.x;
    const int bid = blockIdx.x;
    const int i = bid * 256 + tid;

    int c = (i < N_NODES) ? g_count[i] : 0;
    s[tid] = c;
    __syncthreads();
    for (int off = 1; off < 256; off <<= 1) {
        int t = (tid >= off) ? s[tid - off] : 0;
        __syncthreads();
        s[tid] += t;
        __syncthreads();
    }
    int total = s[255];

    if (tid == 0) {
        if (bid == 0) {
            s_prefix = 0;
            atomicExch(&g_bstate[0], (2ULL << 32) | (unsigned int)total);
        } else {
            atomicExch(&g_bstate[bid], (1ULL << 32) | (unsigned int)total);
            int pre = 0;
            for (int j = bid - 1; j >= 0; j--) {
                unsigned long long st;
                do {
                    st = *((volatile unsigned long long*)&g_bstate[j]);
                } while ((st >> 32) == 0ULL);
                pre += (int)(st & 0xffffffffULL);
                if ((st >> 32) == 2ULL) break;
            }
            s_prefix = pre;
            atomicExch(&g_bstate[bid], (2ULL << 32) | (unsigned int)(pre + total));
        }
    }
    __syncthreads();

    if (i < N_NODES) {
        int rp = s_prefix + s[tid] - c;
        g_rowptr[i] = rp;
        float di = rsqrtf((float)c + 1.0f);
        g_dinv[i] = di;
        g_count[i] = rp;                  // absolute cursor for scatter
        __half2* o = (__half2*)(g_x0h + i * 16);
#pragma unroll
        for (int q = 0; q < 8; q++) {
            float a = (2 * q < 13)     ? di * x[i * 13 + 2 * q]     : 0.0f;
            float b = (2 * q + 1 < 13) ? di * x[i * 13 + 2 * q + 1] : 0.0f;
            o[q] = __floats2half2_rn(a, b);
        }
    }
    if (i == 0) g_rowptr[N_NODES] = N_EDGES;
}

// ---------------- 3. scatter: 4 edges/thread via int4 ----------------
__global__ void k_scatter(const int* __restrict__ ei) {
    int e4 = blockIdx.x * blockDim.x + threadIdx.x;
    if (e4 < N_EDGES / 4) {
        int4 ss = ((const int4*)ei)[e4];
        int4 dd = ((const int4*)(ei + N_EDGES))[e4];
        int p0 = atomicAdd(&g_count[dd.x], 1);
        int p1 = atomicAdd(&g_count[dd.y], 1);
        int p2 = atomicAdd(&g_count[dd.z], 1);
        int p3 = atomicAdd(&g_count[dd.w], 1);
        g_col[p0] = ss.x;
        g_col[p1] = ss.y;
        g_col[p2] = ss.z;
        g_col[p3] = ss.w;
    }
}

// fp32 accumulate one int4 (8 halves)
__device__ __forceinline__ void acc8(float* acc, const __half* base) {
    int4 raw = *reinterpret_cast<const int4*>(base);
    float2 f0 = __half22float2(H2(raw.x));
    float2 f1 = __half22float2(H2(raw.y));
    float2 f2 = __half22float2(H2(raw.z));
    float2 f3 = __half22float2(H2(raw.w));
    acc[0] += f0.x; acc[1] += f0.y; acc[2] += f1.x; acc[3] += f1.y;
    acc[4] += f2.x; acc[5] += f2.y; acc[6] += f3.x; acc[7] += f3.y;
}

// fp32 accumulate 4 half2 partial sums
__device__ __forceinline__ void acch(float* acc, __half2 s0, __half2 s1,
                                     __half2 s2, __half2 s3) {
    float2 f0 = __half22float2(s0);
    float2 f1 = __half22float2(s1);
    float2 f2 = __half22float2(s2);
    float2 f3 = __half22float2(s3);
    acc[0] += f0.x; acc[1] += f0.y; acc[2] += f1.x; acc[3] += f1.y;
    acc[4] += f2.x; acc[5] += f2.y; acc[6] += f3.x; acc[7] += f3.y;
}

// fp32 accumulate 2 half2 partial sums (4 floats)
__device__ __forceinline__ void acch4(float* acc, __half2 s0, __half2 s1) {
    float2 f0 = __half22float2(s0);
    float2 f1 = __half22float2(s1);
    acc[0] += f0.x; acc[1] += f0.y; acc[2] += f1.x; acc[3] += f1.y;
}

// ---------------- 4a. layer-1 aggregation: g_agg0h[v] = di * agg(x0')[v] ----------------
// 2 nodes per warp; 4 lanes/edge, 4 edge groups per node, 8 edges/pass
__global__ void k_agg1x() {
    const int warp = threadIdx.x >> 5;
    const int lane = threadIdx.x & 31;
    const int h = lane >> 4, hl = lane & 15;
    const int v = blockIdx.x * 16 + warp * 2 + h;
    const int sub = hl & 3, grp = hl >> 2;   // feature int2 slot / edge group

    float acc[4] = {0, 0, 0, 0};
    if (grp == 0) {
        int2 raw = *(const int2*)(g_x0h + v * 16 + sub * 4);
        acch4(acc, H2(raw.x), H2(raw.y));
    }
    int beg = g_rowptr[v], end = g_rowptr[v + 1];
    for (int t = beg; t < end; t += 8) {
        int i0 = t + grp, i1 = i0 + 4;
        int c0 = (i0 < end) ? g_col[i0] : ZROW;
        int c1 = (i1 < end) ? g_col[i1] : ZROW;
        int2 r0 = *(const int2*)(g_x0h + c0 * 16 + sub * 4);
        int2 r1 = *(const int2*)(g_x0h + c1 * 16 + sub * 4);
        acch4(acc, __hadd2(H2(r0.x), H2(r1.x)), __hadd2(H2(r0.y), H2(r1.y)));
    }
    // reduce over edge-group bits (2,3) within each 16-lane half
#pragma unroll
    for (int off = 4; off <= 8; off <<= 1)
#pragma unroll
        for (int c = 0; c < 4; c++) acc[c] += __shfl_xor_sync(FULL, acc[c], off);

    if (grp == 0) {
        float di = g_dinv[v];
        __half2 h0 = __floats2half2_rn(di * acc[0], di * acc[1]);
        __half2 h1 = __floats2half2_rn(di * acc[2], di * acc[3]);
        *(int2*)&g_agg0h[v * 16 + sub * 4] = make_int2(*(int*)&h0, *(int*)&h1);
    }
}

// ---------------- 4b. layer-1 GEMM (mma, K=16) + zero restore ----------------
// block = 128 nodes, 8 warps; x1' = di * relu(A@W1 + b1) -> g_x1h
__global__ void k_gemm1(const float* __restrict__ W1,
                        const float* __restrict__ b1) {
    __shared__ __align__(16) __half sB[16 * 72];   // W1 fp16, rows 13..15 zero
    __shared__ float sB1[64];

    {   // zero-restore for next replay (782*256 = 200192 >= N_NODES)
        int gtid = blockIdx.x * 256 + threadIdx.x;
        if (gtid < N_NODES) g_count[gtid] = 0;
        if (gtid < NB_SCAN) g_bstate[gtid] = 0ULL;
    }
    const int tid = threadIdx.x;
    for (int idx = tid; idx < 16 * 32; idx += 256) {
        int row = idx >> 5, c2 = idx & 31;
        float2 w = (row < 13) ? *(const float2*)&W1[row * 64 + c2 * 2]
                              : make_float2(0.0f, 0.0f);
        *(__half2*)&sB[row * 72 + c2 * 2] = __floats2half2_rn(w.x, w.y);
    }
    if (tid < 64) sB1[tid] = b1[tid];
    __syncthreads();

    const int warp = tid >> 5, lane = tid & 31;
    const int m0 = warp * 16;
    const int base = blockIdx.x * 128;
    const int g = lane >> 2, kq = (lane & 3) * 2;

    // A fragment direct from global (K=16): rows g, g+8; cols kq, kq+8
    const __half* ar0 = g_agg0h + (base + m0 + g) * 16 + kq;
    const __half* ar1 = g_agg0h + (base + m0 + g + 8) * 16 + kq;
    unsigned int a0 = *(const unsigned int*)ar0;
    unsigned int a1 = *(const unsigned int*)ar1;
    unsigned int a2 = *(const unsigned int*)(ar0 + 8);
    unsigned int a3 = *(const unsigned int*)(ar1 + 8);

    const unsigned int sb_base = smem_u32(sB);
    const unsigned int b_r = (lane & 15);
    const unsigned int b_c = ((lane >> 4) << 3);

    float c[32];
#pragma unroll
    for (int i = 0; i < 32; i++) c[i] = 0.0f;
#pragma unroll
    for (int jt = 0; jt < 4; jt++) {
        unsigned int b0, b1r, b2r, b3;
        unsigned int baddr = sb_base + ((b_r * 72) + jt * 16 + b_c) * 2;
        asm volatile("ldmatrix.sync.aligned.m8n8.x4.trans.shared.b16 {%0,%1,%2,%3}, [%4];"
                     : "=r"(b0), "=r"(b1r), "=r"(b2r), "=r"(b3) : "r"(baddr));
        mma_16816(&c[(2 * jt) * 4],     a0, a1, a2, a3, b0, b1r);
        mma_16816(&c[(2 * jt + 1) * 4], a0, a1, a2, a3, b2r, b3);
    }

    // epilogue: x1' = di * relu(c + b1) -> g_x1h (fp16)
    const int rowA = m0 + g, rowB = m0 + g + 8;
    const int nodeA = base + rowA, nodeB = base + rowB;
    const float diA = (nodeA < N_NODES) ? g_dinv[nodeA] : 0.0f;
    const float diB = (nodeB < N_NODES) ? g_dinv[nodeB] : 0.0f;
#pragma unroll
    for (int nt = 0; nt < 8; nt++) {
        const int j = nt * 8 + kq;
        float* cp = &c[nt * 4];
        if (nodeA < N_NODES)
            *(__half2*)&g_x1h[nodeA * 64 + j] = __floats2half2_rn(
                diA * fmaxf(cp[0] + sB1[j], 0.0f),
                diA * fmaxf(cp[1] + sB1[j + 1], 0.0f));
        if (nodeB < N_NODES)
            *(__half2*)&g_x1h[nodeB * 64 + j] = __floats2half2_rn(
                diB * fmaxf(cp[2] + sB1[j], 0.0f),
                diB * fmaxf(cp[3] + sB1[j + 1], 0.0f));
    }
}

// ---------------- 5a. layer 2 aggregation: g_aggh[v] = di * agg(x1')[v] ----------------
__global__ void k_agg2() {
    const int warp = threadIdx.x >> 5;
    const int lane = threadIdx.x & 31;
    const int v = blockIdx.x * 8 + warp;
    const int sub = lane & 7, grp = lane >> 3;   // 8 lanes/edge, 4 edges/pass

    float acc[8] = {0, 0, 0, 0, 0, 0, 0, 0};
    if (grp == 0) acc8(acc, g_x1h + v * 64 + sub * 8);   // self term

    int beg = g_rowptr[v], end = g_rowptr[v + 1];
    for (int t = beg; t < end; t += 16) {
        int i0 = t + grp, i1 = i0 + 4, i2 = i0 + 8, i3 = i0 + 12;
        int c0 = (i0 < end) ? g_col[i0] : ZROW;
        int c1 = (i1 < end) ? g_col[i1] : ZROW;
        int c2 = (i2 < end) ? g_col[i2] : ZROW;
        int c3 = (i3 < end) ? g_col[i3] : ZROW;
        int4 r0 = *(const int4*)(g_x1h + c0 * 64 + sub * 8);
        int4 r1 = *(const int4*)(g_x1h + c1 * 64 + sub * 8);
        int4 r2 = *(const int4*)(g_x1h + c2 * 64 + sub * 8);
        int4 r3 = *(const int4*)(g_x1h + c3 * 64 + sub * 8);
        acch(acc,
             __hadd2(__hadd2(H2(r0.x), H2(r1.x)), __hadd2(H2(r2.x), H2(r3.x))),
             __hadd2(__hadd2(H2(r0.y), H2(r1.y)), __hadd2(H2(r2.y), H2(r3.y))),
             __hadd2(__hadd2(H2(r0.z), H2(r1.z)), __hadd2(H2(r2.z), H2(r3.z))),
             __hadd2(__hadd2(H2(r0.w), H2(r1.w)), __hadd2(H2(r2.w), H2(r3.w))));
    }
#pragma unroll
    for (int off = 8; off <= 16; off <<= 1)
#pragma unroll
        for (int c = 0; c < 8; c++) acc[c] += __shfl_xor_sync(FULL, acc[c], off);

    if (lane < 8) {                         // sub == lane here
        float di = g_dinv[v];
        __half2 h0 = __floats2half2_rn(di * acc[0], di * acc[1]);
        __half2 h1 = __floats2half2_rn(di * acc[2], di * acc[3]);
        __half2 h2 = __floats2half2_rn(di * acc[4], di * acc[5]);
        __half2 h3 = __floats2half2_rn(di * acc[6], di * acc[7]);
        int4 pack = make_int4(*(int*)&h0, *(int*)&h1, *(int*)&h2, *(int*)&h3);
        *reinterpret_cast<int4*>(g_aggh + v * 64 + lane * 8) = pack;
    }
}

// ---------------- 5b. layer 2 GEMM (tensor cores) + epilogue + projection ----------------
__global__ void k_gemm2(const float* __restrict__ W2,
                        const float* __restrict__ b2,
                        const float* __restrict__ W3) {
    __shared__ __align__(16) __half sA[128 * 72];   // agg tile, then x2 tile
    __shared__ __align__(16) __half sB[64 * 72];    // W2 fp16
    __shared__ float sW3[64 * 10];
    __shared__ float sB2[64];
    __shared__ float sDi[128];

    const int tid = threadIdx.x;
    const int base = blockIdx.x * 128;

    for (int idx = tid; idx < 128 * 8; idx += 256) {      // A tile (int4 chunks)
        int row = idx >> 3, c8 = idx & 7;
        *(int4*)&sA[row * 72 + c8 * 8] =
            *(const int4*)&g_aggh[(base + row) * 64 + c8 * 8];
    }
    for (int idx = tid; idx < 64 * 32; idx += 256) {      // W2 -> fp16
        int row = idx >> 5, c2 = idx & 31;
        float2 w = *(const float2*)&W2[row * 64 + c2 * 2];
        *(__half2*)&sB[row * 72 + c2 * 2] = __floats2half2_rn(w.x, w.y);
    }
    for (int i = tid; i < 640; i += 256) sW3[i] = W3[i];
    if (tid < 64) sB2[tid] = b2[tid];
    if (tid < 128) {
        int node = base + tid;
        sDi[tid] = (node < N_NODES) ? g_dinv[node] : 1.0f;
    }
    __syncthreads();

    const int warp = tid >> 5, lane = tid & 31;
    const int m0 = warp * 16;
    const unsigned int sa_base = smem_u32(sA);
    const unsigned int sb_base = smem_u32(sB);
    const unsigned int a_off = ((m0 + (lane & 15)) * 72 + ((lane >> 4) << 3)) * 2;
    const unsigned int b_r = (lane & 15);
    const unsigned int b_c = ((lane >> 4) << 3);

    float c[32];
#pragma unroll
    for (int i = 0; i < 32; i++) c[i] = 0.0f;

#pragma unroll
    for (int kc = 0; kc < 4; kc++) {
        const int kk = kc * 16;
        unsigned int a0, a1, a2, a3;
        unsigned int aaddr = sa_base + a_off + kk * 2;
        asm volatile("ldmatrix.sync.aligned.m8n8.x4.shared.b16 {%0,%1,%2,%3}, [%4];"
                     : "=r"(a0), "=r"(a1), "=r"(a2), "=r"(a3) : "r"(aaddr));
#pragma unroll
        for (int jt = 0; jt < 4; jt++) {
            const int j0 = jt * 16;
            unsigned int b0, b1, b2r, b3;
            unsigned int baddr = sb_base + (((kk + b_r) * 72) + j0 + b_c) * 2;
            asm volatile("ldmatrix.sync.aligned.m8n8.x4.trans.shared.b16 {%0,%1,%2,%3}, [%4];"
                         : "=r"(b0), "=r"(b1), "=r"(b2r), "=r"(b3) : "r"(baddr));
            mma_16816(&c[(2 * jt) * 4],     a0, a1, a2, a3, b0, b1);
            mma_16816(&c[(2 * jt + 1) * 4], a0, a1, a2, a3, b2r, b3);
        }
    }

    // Epilogue: x2 = relu(c + b2) + x1 ; write fp16 into sA
    {
        const int g = lane >> 2;
        const int colp = 2 * (lane & 3);
        const int rowA = m0 + g, rowB = m0 + g + 8;
        const int nodeA = base + rowA, nodeB = base + rowB;
        const float rdA = 1.0f / sDi[rowA];
        const float rdB = 1.0f / sDi[rowB];
        const int ncA = (nodeA < N_NODES) ? nodeA : ZROW;
        const int ncB = (nodeB < N_NODES) ? nodeB : ZROW;
#pragma unroll
        for (int nt = 0; nt < 8; nt++) {
            const int j = nt * 8 + colp;
            float* cp = &c[nt * 4];
            float2 rA = __half22float2(*(const __half2*)&g_x1h[ncA * 64 + j]);
            float2 rB = __half22float2(*(const __half2*)&g_x1h[ncB * 64 + j]);
            float xA0 = fmaxf(cp[0] + sB2[j],     0.0f) + rA.x * rdA;
            float xA1 = fmaxf(cp[1] + sB2[j + 1], 0.0f) + rA.y * rdA;
            float xB0 = fmaxf(cp[2] + sB2[j],     0.0f) + rB.x * rdB;
            float xB1 = fmaxf(cp[3] + sB2[j + 1], 0.0f) + rB.y * rdB;
            *(__half2*)&sA[rowA * 72 + j] = __floats2half2_rn(xA0, xA1);
            *(__half2*)&sA[rowB * 72 + j] = __floats2half2_rn(xB0, xB1);
        }
    }
    __syncthreads();

    // Projection: 128 nodes x 10 classes; p' = di * (x2 @ W3)
    for (int ii = tid; ii < 1280; ii += 256) {
        const int rl = ii / 10, j = ii - rl * 10;
        const int node = base + rl;
        if (node < N_NODES) {
            float p = 0.0f;
#pragma unroll
            for (int k2 = 0; k2 < 32; k2++) {
                float2 a = __half22float2(*(const __half2*)&sA[rl * 72 + 2 * k2]);
                p += a.x * sW3[(2 * k2) * 10 + j] + a.y * sW3[(2 * k2 + 1) * 10 + j];
            }
            g_ph[node * 16 + j] = __float2half(sDi[rl] * p);
        }
    }
}

// ---------------- 6. layer 3: 2 nodes/warp; agg(p') -> softmax ----------------
__global__ void k_layer3(const float* __restrict__ b3, float* __restrict__ out) {
    __shared__ __align__(16) float sp[8][2][16];
    const int warp = threadIdx.x >> 5;
    const int lane = threadIdx.x & 31;
    const int h = lane >> 4, hl = lane & 15;
    const int v = blockIdx.x * 16 + warp * 2 + h;
    const int sub = hl & 3, grp = hl >> 2;

    float acc[4] = {0, 0, 0, 0};
    if (grp == 0) {
        int2 raw = *(const int2*)(g_ph + v * 16 + sub * 4);
        acch4(acc, H2(raw.x), H2(raw.y));
    }
    int beg = g_rowptr[v], end = g_rowptr[v + 1];
    for (int t = beg; t < end; t += 8) {
        int i0 = t + grp, i1 = i0 + 4;
        int c0 = (i0 < end) ? g_col[i0] : ZROW;
        int c1 = (i1 < end) ? g_col[i1] : ZROW;
        int2 r0 = *(const int2*)(g_ph + c0 * 16 + sub * 4);
        int2 r1 = *(const int2*)(g_ph + c1 * 16 + sub * 4);
        acch4(acc, __hadd2(H2(r0.x), H2(r1.x)), __hadd2(H2(r0.y), H2(r1.y)));
    }
#pragma unroll
    for (int off = 4; off <= 8; off <<= 1)
#pragma unroll
        for (int c = 0; c < 4; c++) acc[c] += __shfl_xor_sync(FULL, acc[c], off);

    if (grp == 0)
        *(float4*)&sp[warp][h][sub * 4] = make_float4(acc[0], acc[1], acc[2], acc[3]);
    __syncwarp();

    float di = g_dinv[v];
    float z = (hl < 10) ? di * sp[warp][h][hl] + b3[hl] : -INFINITY;
    float mx = z;
#pragma unroll
    for (int off = 8; off; off >>= 1) mx = fmaxf(mx, __shfl_xor_sync(FULL, mx, off));
    float ex = (hl < 10) ? expf(z - mx) : 0.0f;
    float s = ex;
#pragma unroll
    for (int off = 8; off; off >>= 1) s += __shfl_xor_sync(FULL, s, off);
    if (hl < 10) out[v * 10 + hl] = z - mx - logf(s);
}

extern "C" void kernel_launch(void* const* d_in, const int* in_sizes, int n_in,
                              void* d_out, int out_size) {
    const float* x  = (const float*)d_in[0];
    const int*   ei = (const int*)d_in[1];
    const float* W1 = (const float*)d_in[2];
    const float* b1 = (const float*)d_in[3];
    const float* W2 = (const float*)d_in[4];
    const float* b2 = (const float*)d_in[5];
    const float* W3 = (const float*)d_in[6];
    const float* b3 = (const float*)d_in[7];
    float* out = (float*)d_out;

    const int TB = 256;
    int hist4Blocks = (N_EDGES / 4 + TB - 1) / TB;
    int scat4Blocks = (N_EDGES / 4 + TB - 1) / TB;

    k_hist<<<hist4Blocks, TB>>>(ei);
    k_scanfused<<<NB_SCAN, TB>>>(x);
    k_scatter<<<scat4Blocks, TB>>>(ei);
    k_agg1x<<<NGRP16, TB>>>();
    k_gemm1<<<MTILES, TB>>>(W1, b1);
    k_agg2<<<NGRP, TB>>>();
    k_gemm2<<<MTILES, TB>>>(W2, b2, W3);
    k_layer3<<<NGRP16, TB>>>(b3, out);
}